// round 3
// baseline (speedup 1.0000x reference)
#include <cuda_runtime.h>
#include <cuda_bf16.h>

#define N_ATOMS   50000
#define NUM_ELEM  10
#define LMAX      3
#define SH_DIM    16
#define CIN       128
#define COUT      128
#define TILE_M    64
#define NSEG      (NUM_ELEM * (LMAX + 1))
// max tiles: sum_{e,l} ceil(cnt_e*(2l+1)/64) <= N*16/64 + 40 = 12540
#define GRID_GEMM 12560
#define AS_STR    136   // bf16 elems per row (128 + 8 pad) -> conflict-free ldmatrix

__device__ int   g_counts[NUM_ELEM];
__device__ int   g_cursor[NUM_ELEM];
__device__ int   g_offsets[NUM_ELEM];
__device__ int   g_species[N_ATOMS];
__device__ int   g_order[N_ATOMS];
__device__ int   g_tile_prefix[NSEG + 1];
// W packed into per-thread mma B-fragment layout: [seg][ks][nt][lane] -> {hi0,hi1,lo0,lo1}
__device__ uint4 g_wpack[NSEG * 4096];

// ---------------- helpers ----------------

__device__ __forceinline__ void split2(float a, float b, unsigned& hi, unsigned& lo) {
    __nv_bfloat16 ha = __float2bfloat16(a);
    __nv_bfloat16 hb = __float2bfloat16(b);
    float ra = a - __bfloat162float(ha);
    float rb = b - __bfloat162float(hb);
    __nv_bfloat162 hp; hp.x = ha; hp.y = hb;
    __nv_bfloat162 lp; lp.x = __float2bfloat16(ra); lp.y = __float2bfloat16(rb);
    hi = *(unsigned*)&hp;
    lo = *(unsigned*)&lp;
}

__device__ __forceinline__ void mma_bf16(float* c, const unsigned* a, unsigned b0, unsigned b1) {
    asm volatile(
        "mma.sync.aligned.m16n8k16.row.col.f32.bf16.bf16.f32 "
        "{%0,%1,%2,%3}, {%4,%5,%6,%7}, {%8,%9}, {%0,%1,%2,%3};\n"
        : "+f"(c[0]), "+f"(c[1]), "+f"(c[2]), "+f"(c[3])
        : "r"(a[0]), "r"(a[1]), "r"(a[2]), "r"(a[3]), "r"(b0), "r"(b1));
}

__device__ __forceinline__ void ldmatrix_x4(unsigned* r, unsigned saddr) {
    asm volatile(
        "ldmatrix.sync.aligned.m8n8.x4.shared.b16 {%0,%1,%2,%3}, [%4];\n"
        : "=r"(r[0]), "=r"(r[1]), "=r"(r[2]), "=r"(r[3]) : "r"(saddr));
}

// ---------------- prep kernels ----------------

__global__ void k_init() {
    int t = threadIdx.x;
    if (t < NUM_ELEM) { g_counts[t] = 0; g_cursor[t] = 0; }
}

__global__ void k_hist(const float* __restrict__ y) {
    __shared__ int cnt[NUM_ELEM];
    int tid = threadIdx.x;
    if (tid < NUM_ELEM) cnt[tid] = 0;
    __syncthreads();
    int n = blockIdx.x * blockDim.x + tid;
    if (n < N_ATOMS) {
        const float* yr = y + (long)n * NUM_ELEM;
        float best = yr[0]; int s = 0;
#pragma unroll
        for (int e = 1; e < NUM_ELEM; e++) {
            float v = yr[e];
            if (v > best) { best = v; s = e; }
        }
        g_species[n] = s;
        atomicAdd(&cnt[s], 1);
    }
    __syncthreads();
    if (tid < NUM_ELEM && cnt[tid] > 0) atomicAdd(&g_counts[tid], cnt[tid]);
}

__global__ void k_scan() {
    __shared__ int c[NUM_ELEM];
    int t = threadIdx.x;
    if (t < NUM_ELEM) c[t] = g_counts[t];
    __syncthreads();
    if (t == 0) {
        int off = 0;
        for (int e = 0; e < NUM_ELEM; e++) { g_offsets[e] = off; off += c[e]; }
        int tp = 0, seg = 0;
        g_tile_prefix[0] = 0;
        for (int e = 0; e < NUM_ELEM; e++)
            for (int l = 0; l <= LMAX; l++) {
                int rows = c[e] * (2 * l + 1);
                tp += (rows + TILE_M - 1) / TILE_M;
                g_tile_prefix[++seg] = tp;
            }
    }
}

__global__ void k_scatter() {
    __shared__ int cnt[NUM_ELEM];
    __shared__ int base[NUM_ELEM];
    int tid = threadIdx.x;
    if (tid < NUM_ELEM) cnt[tid] = 0;
    __syncthreads();
    int n = blockIdx.x * blockDim.x + tid;
    int s = -1, myrank = 0;
    if (n < N_ATOMS) {
        s = g_species[n];
        myrank = atomicAdd(&cnt[s], 1);
    }
    __syncthreads();
    if (tid < NUM_ELEM) base[tid] = cnt[tid] ? atomicAdd(&g_cursor[tid], cnt[tid]) : 0;
    __syncthreads();
    if (n < N_ATOMS) g_order[g_offsets[s] + base[s] + myrank] = n;
}

// Pack W[e][l] into mma B-fragment layout (hi/lo bf16 split).
__global__ void k_wpack(const float* __restrict__ w) {
    int idx = blockIdx.x * blockDim.x + threadIdx.x;
    if (idx >= NSEG * 4096) return;
    int seg = idx >> 12;
    int rem = idx & 4095;
    int ks = rem >> 9;
    int nt = (rem >> 5) & 15;
    int t  = rem & 31;
    int k0 = ks * 16 + 2 * (t & 3);
    int n  = nt * 8 + (t >> 2);
    const float* W = w + (long)seg * CIN * COUT;
    float v0 = W[(k0    ) * COUT + n];
    float v1 = W[(k0 + 1) * COUT + n];
    float v2 = W[(k0 + 8) * COUT + n];
    float v3 = W[(k0 + 9) * COUT + n];
    unsigned h0, l0, h1, l1;
    split2(v0, v1, h0, l0);
    split2(v2, v3, h1, l1);
    g_wpack[idx] = make_uint4(h0, h1, l0, l1);
}

// ---------------- tensor-core tile GEMM ----------------
// CTA: 64 gathered rows x W[e,l] 128x128. 256 threads / 8 warps, 2 CTAs/SM.
// Warp w: m-tile (w>>1)*16 rows, n-half (w&1)*64 cols (8 n-tiles).
// A pre-split to bf16 hi/lo in SMEM during gather; mainloop = ldmatrix + LDS.128 + HMMA.

#define A_SMEM_HALF (TILE_M * AS_STR)                      // bf16 elems
#define SMEM_BYTES  (2 * A_SMEM_HALF * 2 + 4096 * 16 + TILE_M * 4)

__global__ __launch_bounds__(256, 2)
void k_gemm(const float* __restrict__ x, float* __restrict__ out) {
    extern __shared__ char smem_raw[];
    __nv_bfloat16* Ahi = (__nv_bfloat16*)smem_raw;               // [64][136]
    __nv_bfloat16* Alo = Ahi + A_SMEM_HALF;                      // [64][136]
    uint4* Bs          = (uint4*)(Alo + A_SMEM_HALF);            // 4096 frags
    int*   rowbase     = (int*)(Bs + 4096);

    int t = blockIdx.x;
    if (t >= g_tile_prefix[NSEG]) return;
    int seg = 0;
    while (g_tile_prefix[seg + 1] <= t) seg++;
    int e = seg >> 2, l = seg & 3;
    int row0 = (t - g_tile_prefix[seg]) * TILE_M;
    int R = 2 * l + 1;
    int Mseg = g_counts[e] * R;
    int offe = g_offsets[e];
    int tid = threadIdx.x;

    // per-row x base offsets
    if (tid < TILE_M) {
        int r = row0 + tid;
        int rb = -1;
        if (r < Mseg) {
            int atom = g_order[offe + r / R];
            rb = (atom * SH_DIM + l * l + r % R) * CIN;
        }
        rowbase[tid] = rb;
    }

    // copy pre-packed W frags (LDG.128 -> STS.128)
    {
        const uint4* wp = g_wpack + seg * 4096;
#pragma unroll
        for (int i = 0; i < 16; i++) Bs[tid + i * 256] = wp[tid + i * 256];
    }
    __syncthreads();

    // gather 64 x-rows, splitting fp32 -> bf16 hi/lo. 4 threads/row, 32 cols each.
    {
        int m = tid >> 2, q = tid & 3;
        int rb = rowbase[m];
        __nv_bfloat16* dh = Ahi + m * AS_STR + q * 32;
        __nv_bfloat16* dl = Alo + m * AS_STR + q * 32;
        if (rb >= 0) {
            const float4* src = (const float4*)(x + rb + q * 32);
#pragma unroll
            for (int i = 0; i < 8; i++) {
                float4 v = src[i];
                unsigned h0, l0, h1, l1;
                split2(v.x, v.y, h0, l0);
                split2(v.z, v.w, h1, l1);
                *(uint2*)(dh + i * 4) = make_uint2(h0, h1);
                *(uint2*)(dl + i * 4) = make_uint2(l0, l1);
            }
        } else {
            uint2 z = make_uint2(0u, 0u);
#pragma unroll
            for (int i = 0; i < 8; i++) {
                *(uint2*)(dh + i * 4) = z;
                *(uint2*)(dl + i * 4) = z;
            }
        }
    }
    __syncthreads();

    int w     = tid >> 5;
    int lane  = tid & 31;
    int g     = lane >> 2;
    int tig   = lane & 3;
    int mrow0 = (w >> 1) * 16;      // 16 rows per warp
    int nh    = (w & 1) * 8;        // 8 n-tiles (64 cols) per warp

    // ldmatrix source address (per-lane): row = lane&15, k-offset = (lane>>4)*8
    unsigned a_row  = mrow0 + (lane & 15);
    unsigned a_koff = (lane >> 4) << 3;
    unsigned sa_hi = (unsigned)__cvta_generic_to_shared(Ahi + a_row * AS_STR + a_koff);
    unsigned sa_lo = (unsigned)__cvta_generic_to_shared(Alo + a_row * AS_STR + a_koff);

    float acc[8][4];
#pragma unroll
    for (int nt = 0; nt < 8; nt++)
#pragma unroll
        for (int i = 0; i < 4; i++) acc[nt][i] = 0.f;

#pragma unroll
    for (int ks = 0; ks < 8; ks++) {
        unsigned ah[4], al[4];
        ldmatrix_x4(ah, sa_hi + ks * 32);   // 16 bf16 = 32B per k-step
        ldmatrix_x4(al, sa_lo + ks * 32);
#pragma unroll
        for (int ntl = 0; ntl < 8; ntl++) {
            uint4 B = Bs[(ks * 16 + nh + ntl) * 32 + lane];
            mma_bf16(acc[ntl], ah, B.x, B.y);   // Ah*Wh
            mma_bf16(acc[ntl], ah, B.z, B.w);   // Ah*Wl
            mma_bf16(acc[ntl], al, B.x, B.y);   // Al*Wh
        }
    }

    const float scale = 0.08838834764831845f;  // 1/sqrt(128)
    int rlo = rowbase[mrow0 + g];
    int rhi = rowbase[mrow0 + g + 8];
#pragma unroll
    for (int ntl = 0; ntl < 8; ntl++) {
        int col = (nh + ntl) * 8 + 2 * tig;
        if (rlo >= 0)
            *(float2*)(out + rlo + col) =
                make_float2(acc[ntl][0] * scale, acc[ntl][1] * scale);
        if (rhi >= 0)
            *(float2*)(out + rhi + col) =
                make_float2(acc[ntl][2] * scale, acc[ntl][3] * scale);
    }
}

// ---------------- launch ----------------

extern "C" void kernel_launch(void* const* d_in, const int* in_sizes, int n_in,
                              void* d_out, int out_size) {
    const float* x = (const float*)d_in[0];   // [N, 16, 128]
    const float* y = (const float*)d_in[1];   // [N, 10]
    const float* w = (const float*)d_in[2];   // [10, 4, 128, 128]
    float* out = (float*)d_out;               // [N, 16, 128]

    cudaFuncSetAttribute(k_gemm, cudaFuncAttributeMaxDynamicSharedMemorySize,
                         SMEM_BYTES);

    k_init<<<1, 32>>>();
    k_hist<<<(N_ATOMS + 255) / 256, 256>>>(y);
    k_scan<<<1, 32>>>();
    k_scatter<<<(N_ATOMS + 255) / 256, 256>>>();
    k_wpack<<<(NSEG * 4096 + 255) / 256, 256>>>(w);
    k_gemm<<<GRID_GEMM, 256, SMEM_BYTES>>>(x, out);
}